// round 10
// baseline (speedup 1.0000x reference)
#include <cuda_runtime.h>
#include <cuda_fp16.h>
#include <stdint.h>

// Fixed problem shape: N=100000 nodes, E=1600000 edges, dims 128 -> 128 -> 40.
#define NMAX 100352
#define EMAX 1600000

// ---------------- device scratch (zero-initialized at load; scan/scatter
// re-zero g_deg/g_tilestate themselves so every replay starts clean) --------
__device__ int    g_deg[NMAX];                 // 0 at call entry (self-cleaned)
__device__ unsigned int g_tilestate[128];      // 0 at call entry (self-cleaned)
__device__ __align__(16) int g_rowptr[NMAX + 1];
__device__ int    g_cursor[NMAX];
__device__ __align__(16) int g_csrsrc[EMAX];
__device__ float  g_dinv[NMAX];
__device__ __align__(16) __half g_ph[(size_t)NMAX * 128];  // fp16 messages m_i = dinv_i * h_i
__device__ float  g_hidden_scratch[(size_t)NMAX * 128];    // fallback hidden storage

// ---------------- inline int64 detection (block-uniform) ----------------
__device__ __forceinline__ int detect_idx64(const void* ei) {
    const int* w = (const int*)ei;
    int any = 0;
#pragma unroll
    for (int k = 0; k < 64; ++k) any |= w[2 * k + 1];
    return (any == 0) ? 1 : 0;
}

// ---------------- degree count (2 edges per thread) ----------------
__global__ void k_deg_count(const void* __restrict__ ei, int E, int n) {
    __shared__ int s_idx64;
    if (threadIdx.x == 0) s_idx64 = detect_idx64(ei);
    __syncthreads();
    int t = blockIdx.x * blockDim.x + threadIdx.x;
    int e0 = t * 2;
    if (e0 + 1 < E) {
        int d0, d1;
        if (s_idx64) {
            const long long* dst = (const long long*)ei + E;
            longlong2 v = ((const longlong2*)dst)[t];
            d0 = (int)v.x; d1 = (int)v.y;
        } else {
            const int* dst = (const int*)ei + E;
            int2 v = ((const int2*)dst)[t];
            d0 = v.x; d1 = v.y;
        }
        if ((unsigned)d0 < (unsigned)n) atomicAdd(&g_deg[d0], 1);
        if ((unsigned)d1 < (unsigned)n) atomicAdd(&g_deg[d1], 1);
    } else if (e0 < E) {
        int d = s_idx64 ? (int)((const long long*)ei)[(long long)E + e0]
                        : ((const int*)ei)[(long long)E + e0];
        if ((unsigned)d < (unsigned)n) atomicAdd(&g_deg[d], 1);
    }
}

// ---------------- single-pass decoupled-lookback scan + finish + self-clean ----
__global__ void k_scan(int n, int E) {
    __shared__ int ssum[256];
    __shared__ int s_excl;
    int tid = threadIdx.x;
    int tile = blockIdx.x;
    int base = tile * 1024 + tid * 4;
    int v0 = (base + 0 < n) ? g_deg[base + 0] : 0;
    int v1 = (base + 1 < n) ? g_deg[base + 1] : 0;
    int v2 = (base + 2 < n) ? g_deg[base + 2] : 0;
    int v3 = (base + 3 < n) ? g_deg[base + 3] : 0;
    int p0 = 0, p1 = v0, p2 = v0 + v1, p3 = v0 + v1 + v2;
    int total = p3 + v3;
    ssum[tid] = total;
    __syncthreads();
    for (int off = 1; off < 256; off <<= 1) {
        int v = 0;
        if (tid >= off) v = ssum[tid - off];
        __syncthreads();
        if (tid >= off) ssum[tid] += v;
        __syncthreads();
    }
    int excl_in_tile = ssum[tid] - total;
    int tile_total = ssum[255];

    if (tid == 0) {
        if (tile == 0) {
            __threadfence();
            *(volatile unsigned int*)&g_tilestate[0] = (2u << 30) | (unsigned)tile_total;
            s_excl = 0;
        } else {
            *(volatile unsigned int*)&g_tilestate[tile] = (1u << 30) | (unsigned)tile_total;
            __threadfence();
            int excl = 0;
            int t = tile - 1;
            while (true) {
                unsigned int s = *(volatile unsigned int*)&g_tilestate[t];
                unsigned int f = s >> 30;
                if (f == 0) continue;
                excl += (int)(s & 0x3FFFFFFFu);
                if (f == 2) break;
                --t;
            }
            __threadfence();
            *(volatile unsigned int*)&g_tilestate[tile] = (2u << 30) | (unsigned)(excl + tile_total);
            s_excl = excl;
        }
    }
    __syncthreads();
    int excl = s_excl + excl_in_tile;

#pragma unroll
    for (int q = 0; q < 4; ++q) {
        int i = base + q;
        if (i < n) {
            int pv = excl + ((q == 0) ? p0 : (q == 1) ? p1 : (q == 2) ? p2 : p3);
            g_rowptr[i] = pv;
            g_cursor[i] = pv;
            int dv = (q == 0) ? v0 : (q == 1) ? v1 : (q == 2) ? v2 : v3;
            g_dinv[i] = rsqrtf((float)(dv + 1));
            g_deg[i] = 0;                      // self-clean for next call
        }
    }
    if (tile == 0 && tid == 0) g_rowptr[n] = E;
}

// ---------------- scatter (2 edges per thread) ----------------
__global__ void k_scatter(const void* __restrict__ ei, int E, int n) {
    __shared__ int s_idx64;
    if (threadIdx.x == 0) s_idx64 = detect_idx64(ei);
    __syncthreads();
    if (blockIdx.x == 0 && threadIdx.x < 128) g_tilestate[threadIdx.x] = 0;
    int t = blockIdx.x * blockDim.x + threadIdx.x;
    int e0 = t * 2;
    if (e0 + 1 < E) {
        int s0, s1, d0, d1;
        if (s_idx64) {
            const long long* src = (const long long*)ei;
            const long long* dst = src + E;
            longlong2 sv = ((const longlong2*)src)[t];
            longlong2 dv = ((const longlong2*)dst)[t];
            s0 = (int)sv.x; s1 = (int)sv.y; d0 = (int)dv.x; d1 = (int)dv.y;
        } else {
            const int* src = (const int*)ei;
            const int* dst = src + E;
            int2 sv = ((const int2*)src)[t];
            int2 dv = ((const int2*)dst)[t];
            s0 = sv.x; s1 = sv.y; d0 = dv.x; d1 = dv.y;
        }
        if ((unsigned)d0 < (unsigned)n && (unsigned)s0 < (unsigned)n) {
            int pos = atomicAdd(&g_cursor[d0], 1);
            if (pos < EMAX) g_csrsrc[pos] = s0;
        }
        if ((unsigned)d1 < (unsigned)n && (unsigned)s1 < (unsigned)n) {
            int pos = atomicAdd(&g_cursor[d1], 1);
            if (pos < EMAX) g_csrsrc[pos] = s1;
        }
    } else if (e0 < E) {
        int s, d;
        if (s_idx64) {
            s = (int)((const long long*)ei)[e0];
            d = (int)((const long long*)ei)[(long long)E + e0];
        } else {
            s = ((const int*)ei)[e0];
            d = ((const int*)ei)[(long long)E + e0];
        }
        if ((unsigned)d < (unsigned)n && (unsigned)s < (unsigned)n) {
            int pos = atomicAdd(&g_cursor[d], 1);
            if (pos < EMAX) g_csrsrc[pos] = s;
        }
    }
}

// ---------------- TF32 helpers ----------------
__device__ __forceinline__ unsigned int f2tf32(float f) {
    unsigned int u;
    asm("cvt.rna.tf32.f32 %0, %1;" : "=r"(u) : "f"(f));
    return u;
}
#define XS_STRIDE 36
#define WS_STRIDE 132

// ---------------- TF32 GEMM layer 1: g_ph = fp16(dinv * (X @ W1)) ----
// Block 256 threads = 8 warps (2 M x 4 N); block tile 128 x 128.
__launch_bounds__(256)
__global__ void k_gemm_tc(const float* __restrict__ X, const float* __restrict__ W, int n) {
    __shared__ unsigned int Xs[128 * XS_STRIDE];
    __shared__ unsigned int Ws[32 * WS_STRIDE];
    const int tid = threadIdx.x;
    const int warp = tid >> 5;
    const int lane = tid & 31;
    const int wm = warp >> 2;
    const int wn = warp & 3;
    const int grp = lane >> 2;
    const int qid = lane & 3;
    const int n0 = blockIdx.x * 128;

    float acc[4][4][4];
#pragma unroll
    for (int mt = 0; mt < 4; ++mt)
#pragma unroll
        for (int nt = 0; nt < 4; ++nt)
#pragma unroll
            for (int r = 0; r < 4; ++r) acc[mt][nt][r] = 0.f;

    for (int kc = 0; kc < 4; ++kc) {
        __syncthreads();
#pragma unroll
        for (int i = 0; i < 16; ++i) {
            int idx = tid + i * 256;
            int row = idx >> 5, col = idx & 31;
            int node = n0 + row;
            float v = (node < n) ? X[(size_t)node * 128 + kc * 32 + col] : 0.f;
            Xs[row * XS_STRIDE + col] = f2tf32(v);
        }
#pragma unroll
        for (int i = 0; i < 16; ++i) {
            int idx = tid + i * 256;
            int k = idx >> 7, col = idx & 127;
            Ws[k * WS_STRIDE + col] = f2tf32(W[(size_t)(kc * 32 + k) * 128 + col]);
        }
        __syncthreads();
#pragma unroll
        for (int kk = 0; kk < 4; ++kk) {
            const int k8 = kk * 8;
            unsigned int af[4][4];
#pragma unroll
            for (int mt = 0; mt < 4; ++mt) {
                int rbase = wm * 64 + mt * 16;
                af[mt][0] = Xs[(rbase + grp) * XS_STRIDE + k8 + qid];
                af[mt][1] = Xs[(rbase + grp + 8) * XS_STRIDE + k8 + qid];
                af[mt][2] = Xs[(rbase + grp) * XS_STRIDE + k8 + qid + 4];
                af[mt][3] = Xs[(rbase + grp + 8) * XS_STRIDE + k8 + qid + 4];
            }
            unsigned int bf[4][2];
#pragma unroll
            for (int nt = 0; nt < 4; ++nt) {
                int cbase = wn * 32 + nt * 8;
                bf[nt][0] = Ws[(k8 + qid) * WS_STRIDE + cbase + grp];
                bf[nt][1] = Ws[(k8 + qid + 4) * WS_STRIDE + cbase + grp];
            }
#pragma unroll
            for (int mt = 0; mt < 4; ++mt)
#pragma unroll
                for (int nt = 0; nt < 4; ++nt) {
                    asm volatile(
                        "mma.sync.aligned.m16n8k8.row.col.f32.tf32.tf32.f32 "
                        "{%0,%1,%2,%3}, {%4,%5,%6,%7}, {%8,%9}, {%0,%1,%2,%3};"
                        : "+f"(acc[mt][nt][0]), "+f"(acc[mt][nt][1]),
                          "+f"(acc[mt][nt][2]), "+f"(acc[mt][nt][3])
                        : "r"(af[mt][0]), "r"(af[mt][1]), "r"(af[mt][2]), "r"(af[mt][3]),
                          "r"(bf[nt][0]), "r"(bf[nt][1]));
                }
        }
    }
    // epilogue: scale by dinv (fp32) then single fp16 round.
#pragma unroll
    for (int mt = 0; mt < 4; ++mt) {
        int r0 = n0 + wm * 64 + mt * 16 + grp;
        int r1 = r0 + 8;
        float d0 = (r0 < n) ? g_dinv[r0] : 0.f;
        float d1 = (r1 < n) ? g_dinv[r1] : 0.f;
#pragma unroll
        for (int nt = 0; nt < 4; ++nt) {
            int col = wn * 32 + nt * 8 + 2 * qid;
            if (r0 < n) {
                __half2 h = __float22half2_rn(make_float2(acc[mt][nt][0] * d0, acc[mt][nt][1] * d0));
                *(__half2*)(g_ph + (size_t)r0 * 128 + col) = h;
            }
            if (r1 < n) {
                __half2 h = __float22half2_rn(make_float2(acc[mt][nt][2] * d1, acc[mt][nt][3] * d1));
                *(__half2*)(g_ph + (size_t)r1 * 128 + col) = h;
            }
        }
    }
}

// ---------------- TF32 GEMM layer 2: g_ph = fp16(dinv * (hidden @ W2)) ----
#define W2S_STRIDE 44
__launch_bounds__(256)
__global__ void k_gemm40_tc(const float* __restrict__ X, const float* __restrict__ W, int n) {
    __shared__ unsigned int Xs[128 * XS_STRIDE];
    __shared__ unsigned int Ws[32 * W2S_STRIDE];
    const int tid = threadIdx.x;
    const int warp = tid >> 5;
    const int lane = tid & 31;
    const int grp = lane >> 2;
    const int qid = lane & 3;
    const int n0 = blockIdx.x * 128;

    float acc[5][4];
#pragma unroll
    for (int nt = 0; nt < 5; ++nt)
#pragma unroll
        for (int r = 0; r < 4; ++r) acc[nt][r] = 0.f;

    for (int kc = 0; kc < 4; ++kc) {
        __syncthreads();
#pragma unroll
        for (int i = 0; i < 16; ++i) {
            int idx = tid + i * 256;
            int row = idx >> 5, col = idx & 31;
            int node = n0 + row;
            float v = (node < n) ? X[(size_t)node * 128 + kc * 32 + col] : 0.f;
            Xs[row * XS_STRIDE + col] = f2tf32(v);
        }
        for (int idx = tid; idx < 32 * 40; idx += 256) {
            int k = idx / 40, c = idx % 40;
            Ws[k * W2S_STRIDE + c] = f2tf32(W[(size_t)(kc * 32 + k) * 40 + c]);
        }
        __syncthreads();
#pragma unroll
        for (int kk = 0; kk < 4; ++kk) {
            const int k8 = kk * 8;
            const int rbase = warp * 16;
            unsigned int a0 = Xs[(rbase + grp) * XS_STRIDE + k8 + qid];
            unsigned int a1 = Xs[(rbase + grp + 8) * XS_STRIDE + k8 + qid];
            unsigned int a2 = Xs[(rbase + grp) * XS_STRIDE + k8 + qid + 4];
            unsigned int a3 = Xs[(rbase + grp + 8) * XS_STRIDE + k8 + qid + 4];
#pragma unroll
            for (int nt = 0; nt < 5; ++nt) {
                unsigned int b0 = Ws[(k8 + qid) * W2S_STRIDE + nt * 8 + grp];
                unsigned int b1 = Ws[(k8 + qid + 4) * W2S_STRIDE + nt * 8 + grp];
                asm volatile(
                    "mma.sync.aligned.m16n8k8.row.col.f32.tf32.tf32.f32 "
                    "{%0,%1,%2,%3}, {%4,%5,%6,%7}, {%8,%9}, {%0,%1,%2,%3};"
                    : "+f"(acc[nt][0]), "+f"(acc[nt][1]), "+f"(acc[nt][2]), "+f"(acc[nt][3])
                    : "r"(a0), "r"(a1), "r"(a2), "r"(a3), "r"(b0), "r"(b1));
            }
        }
    }
    int r0 = n0 + warp * 16 + grp;
    int r1 = r0 + 8;
    float d0 = (r0 < n) ? g_dinv[r0] : 0.f;
    float d1 = (r1 < n) ? g_dinv[r1] : 0.f;
#pragma unroll
    for (int nt = 0; nt < 5; ++nt) {
        int col = nt * 8 + 2 * qid;
        if (r0 < n) {
            __half2 h = __float22half2_rn(make_float2(acc[nt][0] * d0, acc[nt][1] * d0));
            *(__half2*)(g_ph + (size_t)r0 * 40 + col) = h;
        }
        if (r1 < n) {
            __half2 h = __float22half2_rn(make_float2(acc[nt][2] * d1, acc[nt][3] * d1));
            *(__half2*)(g_ph + (size_t)r1 * 40 + col) = h;
        }
    }
}

// ---------------- aggregation (messages pre-scaled by dinv[src]) ----------------
__device__ __forceinline__ float4 cvt4(uint2 r) {
    float2 a = __half22float2(*(const __half2*)&r.x);
    float2 b = __half22float2(*(const __half2*)&r.y);
    return make_float4(a.x, a.y, b.x, b.y);
}
__device__ __forceinline__ void acc4(float4& acc, float4 v) {
    acc.x += v.x; acc.y += v.y; acc.z += v.z; acc.w += v.w;
}

__global__ void k_agg128(const float* __restrict__ bias, float* __restrict__ out, int n) {
    int warp = (blockIdx.x * blockDim.x + threadIdx.x) >> 5;
    if (warp >= n) return;
    int lane = threadIdx.x & 31;
    const uint2* p = (const uint2*)g_ph;
    float diw = g_dinv[warp];
    float4 acc = cvt4(p[(size_t)warp * 32 + lane]);     // self message m_d
    int j = g_rowptr[warp];
    int end = g_rowptr[warp + 1];
    for (; j < end && (j & 3); ++j)
        acc4(acc, cvt4(__ldg(&p[(size_t)g_csrsrc[j] * 32 + lane])));
    for (; j + 4 <= end; j += 4) {
        int4 s4 = __ldg((const int4*)&g_csrsrc[j]);
        float4 v0 = cvt4(__ldg(&p[(size_t)s4.x * 32 + lane]));
        float4 v1 = cvt4(__ldg(&p[(size_t)s4.y * 32 + lane]));
        float4 v2 = cvt4(__ldg(&p[(size_t)s4.z * 32 + lane]));
        float4 v3 = cvt4(__ldg(&p[(size_t)s4.w * 32 + lane]));
        acc.x += (v0.x + v1.x) + (v2.x + v3.x);
        acc.y += (v0.y + v1.y) + (v2.y + v3.y);
        acc.z += (v0.z + v1.z) + (v2.z + v3.z);
        acc.w += (v0.w + v1.w) + (v2.w + v3.w);
    }
    for (; j < end; ++j)
        acc4(acc, cvt4(__ldg(&p[(size_t)g_csrsrc[j] * 32 + lane])));
    float4 bb = ((const float4*)bias)[lane];
    float4 o;
    o.x = fmaxf(fmaf(acc.x, diw, bb.x), 0.f);
    o.y = fmaxf(fmaf(acc.y, diw, bb.y), 0.f);
    o.z = fmaxf(fmaf(acc.z, diw, bb.z), 0.f);
    o.w = fmaxf(fmaf(acc.w, diw, bb.w), 0.f);
    ((float4*)out)[(size_t)warp * 32 + lane] = o;
}

__global__ void k_agg40(const float* __restrict__ bias, float* __restrict__ out, int n) {
    int warp = (blockIdx.x * blockDim.x + threadIdx.x) >> 5;
    if (warp >= n) return;
    int lane = threadIdx.x & 31;
    bool act = lane < 20;
    const unsigned int* p = (const unsigned int*)g_ph;
    float diw = g_dinv[warp];
    float2 acc = make_float2(0.f, 0.f);
    if (act) acc = __half22float2(*(const __half2*)&p[(size_t)warp * 20 + lane]);
    int j = g_rowptr[warp];
    int end = g_rowptr[warp + 1];
    for (; j < end && (j & 3); ++j) {
        int s = g_csrsrc[j];
        if (act) {
            unsigned int r = __ldg(&p[(size_t)s * 20 + lane]);
            float2 v = __half22float2(*(const __half2*)&r);
            acc.x += v.x; acc.y += v.y;
        }
    }
    for (; j + 4 <= end; j += 4) {
        int4 s4 = __ldg((const int4*)&g_csrsrc[j]);
        if (act) {
            unsigned int r0 = __ldg(&p[(size_t)s4.x * 20 + lane]);
            unsigned int r1 = __ldg(&p[(size_t)s4.y * 20 + lane]);
            unsigned int r2 = __ldg(&p[(size_t)s4.z * 20 + lane]);
            unsigned int r3 = __ldg(&p[(size_t)s4.w * 20 + lane]);
            float2 v0 = __half22float2(*(const __half2*)&r0);
            float2 v1 = __half22float2(*(const __half2*)&r1);
            float2 v2 = __half22float2(*(const __half2*)&r2);
            float2 v3 = __half22float2(*(const __half2*)&r3);
            acc.x += (v0.x + v1.x) + (v2.x + v3.x);
            acc.y += (v0.y + v1.y) + (v2.y + v3.y);
        }
    }
    for (; j < end; ++j) {
        int s = g_csrsrc[j];
        if (act) {
            unsigned int r = __ldg(&p[(size_t)s * 20 + lane]);
            float2 v = __half22float2(*(const __half2*)&r);
            acc.x += v.x; acc.y += v.y;
        }
    }
    if (act) {
        float2 bb = ((const float2*)bias)[lane];
        float2 o;
        o.x = fmaf(acc.x, diw, bb.x);
        o.y = fmaf(acc.y, diw, bb.y);
        ((float2*)out)[(size_t)warp * 20 + lane] = o;
    }
}

// ---------------- launch ----------------
extern "C" void kernel_launch(void* const* d_in, const int* in_sizes, int n_in,
                              void* d_out, int out_size) {
    const float* x  = (const float*)d_in[0];
    const void*  ei = d_in[1];
    const float* W1 = (const float*)d_in[2];
    const float* b1 = (const float*)d_in[3];
    const float* W2 = (const float*)d_in[4];
    const float* b2 = (const float*)d_in[5];

    int n = in_sizes[0] / 128;
    int E = in_sizes[1] / 2;

    float* out    = (float*)d_out;
    float* logits = out;                       // [n, 40]
    float* hidden;
    if ((size_t)out_size >= (size_t)n * (40 + 128)) {
        hidden = out + (size_t)n * 40;         // [n, 128]
    } else {
        cudaGetSymbolAddress((void**)&hidden, g_hidden_scratch);
    }

    int nb_tc = (n + 127) / 128;
    int nb_e2 = (E / 2 + 255) / 256 + 1;
    int nb_scan = (n + 1023) / 1024;
    int nb_warp = (n + 7) / 8;

    cudaStream_t s2;
    cudaEvent_t evScan, evGemm;
    cudaStreamCreateWithFlags(&s2, cudaStreamNonBlocking);
    cudaEventCreateWithFlags(&evScan, cudaEventDisableTiming);
    cudaEventCreateWithFlags(&evGemm, cudaEventDisableTiming);

    // main: deg -> scan (produces dinv)
    k_deg_count<<<nb_e2, 256>>>(ei, E, n);
    k_scan     <<<nb_scan, 256>>>(n, E);
    cudaEventRecord(evScan, 0);

    // main: scatter  ||  s2: gemm_tc (needs dinv; submission #4 -> ncu profiles it)
    k_scatter<<<nb_e2, 256>>>(ei, E, n);
    cudaStreamWaitEvent(s2, evScan, 0);
    k_gemm_tc<<<nb_tc, 256, 0, s2>>>(x, W1, n);
    cudaEventRecord(evGemm, s2);

    // join, then serial tail
    cudaStreamWaitEvent(0, evGemm, 0);
    k_agg128   <<<nb_warp, 256>>>(b1, hidden, n);
    k_gemm40_tc<<<nb_tc, 256>>>(hidden, W2, n);
    k_agg40    <<<nb_warp, 256>>>(b2, logits, n);

    cudaEventDestroy(evScan);
    cudaEventDestroy(evGemm);
    cudaStreamDestroy(s2);
}